// round 1
// baseline (speedup 1.0000x reference)
#include <cuda_runtime.h>

// PRNN_1769526526374: J2 plane-strain plasticity RNN.
// x:[4096,512,3] f32, W1:[384,3] f32, W2:[3,384] f32 -> out:[4096,512,3] f32.
// One block per batch element b (4096 blocks), one thread per material point
// (128 threads). State (ep[4], kappa) in registers across the 512-step scan.

namespace {
constexpr int Bb  = 4096;
constexpr int Ss  = 512;
constexpr int TPB = 128;

__device__ __forceinline__ float warp_sum(float v) {
    v += __shfl_xor_sync(0xffffffffu, v, 16);
    v += __shfl_xor_sync(0xffffffffu, v, 8);
    v += __shfl_xor_sync(0xffffffffu, v, 4);
    v += __shfl_xor_sync(0xffffffffu, v, 2);
    v += __shfl_xor_sync(0xffffffffu, v, 1);
    return v;
}
} // namespace

__global__ void __launch_bounds__(TPB, 8) prnn_kernel(
    const float* __restrict__ x,    // [B,S,3]
    const float* __restrict__ W1,   // [384,3]
    const float* __restrict__ W2,   // [3,384]
    float* __restrict__ out)        // [B,S,3]
{
    // Material constants (computed in double, rounded once to f32, matching
    // JAX's weak-typed python-scalar * f32-array behavior).
    const float TWO_MU   = (float)(2.0 * (3130.0 / (2.0 * 1.3)));       // 2*MU
    const float THREE_MU = (float)(3.0 * (3130.0 / (2.0 * 1.3)));       // 3*MU
    const float LAM      = (float)(3130.0 * 0.3 / (1.3 * 0.4));
    const float Ah = 64.8f, Bh = 33.6f;
    const float INV_C = (float)(1.0 / 0.003407);
    const float BC    = (float)(33.6 / 0.003407);                        // B/C

    __shared__ float sx[Ss * 3];          // x[b,:,:], 6 KB
    __shared__ float red[2][4][3];        // double-buffered warp partials

    const int b    = blockIdx.x;
    const int tid  = threadIdx.x;
    const int lane = tid & 31;
    const int wp   = tid >> 5;

    // Preload this batch element's strain history (coalesced).
    const float* xb = x + (long)b * (Ss * 3);
    for (int i = tid; i < Ss * 3; i += TPB) sx[i] = xb[i];

    // Per-point weight slices: W1 rows m*3+{0,1,2}; W2 cols m*3+{0,1,2}.
    float w1[9], w2[9];
#pragma unroll
    for (int i = 0; i < 9; ++i) w1[i] = W1[tid * 9 + i];
#pragma unroll
    for (int o = 0; o < 3; ++o)
#pragma unroll
        for (int j = 0; j < 3; ++j) w2[o * 3 + j] = W2[o * 384 + tid * 3 + j];

    float ep0 = 0.f, ep1 = 0.f, ep2 = 0.f, ep3 = 0.f, kap = 0.f;
    float* outb = out + (long)b * (Ss * 3);

    __syncthreads();

    for (int s = 0; s < Ss; ++s) {
        const float x0 = sx[3 * s + 0];
        const float x1 = sx[3 * s + 1];
        const float x2 = sx[3 * s + 2];

        // fc1: engineering strain for this material point
        const float e0 = w1[0] * x0 + w1[1] * x1 + w1[2] * x2;  // exx
        const float e1 = w1[3] * x0 + w1[4] * x1 + w1[5] * x2;  // eyy
        const float g2 = w1[6] * x0 + w1[7] * x1 + w1[8] * x2;  // gxy

        // elastic trial stress (Voigt-4: xx, yy, zz, xy tensorial)
        const float ee0 = e0 - ep0;
        const float ee1 = e1 - ep1;
        const float ee2 = -ep2;
        const float ee3 = 0.5f * g2 - ep3;
        const float tr  = ee0 + ee1 + ee2;
        const float lt  = LAM * tr;
        float sg0 = TWO_MU * ee0 + lt;
        float sg1 = TWO_MU * ee1 + lt;
        float sg2 = TWO_MU * ee2 + lt;
        float sg3 = TWO_MU * ee3;
        const float p  = (sg0 + sg1 + sg2) * (1.0f / 3.0f);
        const float s0 = sg0 - p, s1 = sg1 - p, s2 = sg2 - p, s3 = sg3;
        const float q  = sqrtf(1.5f * (s0 * s0 + s1 * s1 + s2 * s2 + 2.f * s3 * s3));
        const float expk = __expf(-kap * INV_C);
        const float f    = q - (Ah - Bh * expk);

        // Newton return mapping. Reference does 12 fixed iters from dg=0; the
        // iteration is contractive to a unique root, so a converged loop gives
        // the same value. Skip entirely if the whole warp is elastic.
        float dg = 0.f;
        if (__any_sync(0xffffffffu, f > 0.f)) {
#pragma unroll 1
            for (int it = 0; it < 12; ++it) {
                const float ek  = __expf(-(kap + dg) * INV_C);
                const float r   = q - THREE_MU * dg - Ah + Bh * ek;
                const float dr  = -THREE_MU - BC * ek;
                const float dgn = fmaxf(dg - __fdividef(r, dr), 0.f);
                const bool done = fabsf(dgn - dg) <= (1e-10f + 4e-7f * dgn);
                dg = dgn;
                if (__all_sync(0xffffffffu, done)) break;
            }
            dg = (f > 0.f) ? dg : 0.f;
        }

        // radial return + state update
        const float invq = __fdividef(1.f, fmaxf(q, 1e-12f));
        const float c    = dg * invq;
        const float a3   = THREE_MU * c;
        sg0 -= a3 * s0;
        sg1 -= a3 * s1;
        sg3 -= a3 * s3;                 // zz stress not needed for output
        const float bc = 1.5f * c;
        ep0 += bc * s0;
        ep1 += bc * s1;
        ep2 += bc * s2;
        ep3 += bc * s3;
        kap += dg;

        // output projection partials: out[b,s,o] += W2[o, m*3+j] * stress_j
        float p0 = w2[0] * sg0 + w2[1] * sg1 + w2[2] * sg3;
        float p1 = w2[3] * sg0 + w2[4] * sg1 + w2[5] * sg3;
        float p2 = w2[6] * sg0 + w2[7] * sg1 + w2[8] * sg3;
        p0 = warp_sum(p0);
        p1 = warp_sum(p1);
        p2 = warp_sum(p2);

        const int buf = s & 1;
        if (lane == 0) {
            red[buf][wp][0] = p0;
            red[buf][wp][1] = p1;
            red[buf][wp][2] = p2;
        }
        __syncthreads();
        if (tid < 3) {
            outb[3 * s + tid] = red[buf][0][tid] + red[buf][1][tid] +
                                red[buf][2][tid] + red[buf][3][tid];
        }
        // Double buffering makes a second barrier unnecessary: writers of
        // red[buf] at step s+2 can only proceed after everyone (incl. the
        // readers above) passed the barrier at step s+1.
    }
}

extern "C" void kernel_launch(void* const* d_in, const int* in_sizes, int n_in,
                              void* d_out, int out_size) {
    const float* x  = (const float*)d_in[0];
    const float* W1 = (const float*)d_in[1];
    const float* W2 = (const float*)d_in[2];
    prnn_kernel<<<Bb, TPB>>>(x, W1, W2, (float*)d_out);
}

// round 2
// speedup vs baseline: 1.2477x; 1.2477x over previous
#include <cuda_runtime.h>

// PRNN_1769526526374: J2 plane-strain plasticity RNN.
// x:[4096,512,3] f32, W1:[384,3] f32, W2:[3,384] f32 -> out:[4096,512,3] f32.
// One block per batch element (4096 blocks), one thread per material point
// (128 threads). State (ep[4], kappa) in registers across the 512-step scan.
//
// R2 changes vs R1 (issue-bound, ~190 instr/step):
//  - analytic return mapping once exp(-kappa/C) underflows (kappa > 20*C);
//    Newton only during the short hardening transition
//  - chunked smem reduction (T=8): 3 STS/step + 2 barriers/chunk replaces
//    15 SHFL + 1 barrier per step
//  - rsqrtf gives q and 1/q from one MUFU (no divide, no sqrt refine)

namespace {
constexpr int Bb  = 4096;
constexpr int Ss  = 512;
constexpr int TPB = 128;
constexpr int T   = 8;            // steps per reduction chunk
constexpr int ROW = 3 * TPB + 4;  // 388 floats; pad keeps reduce reads conflict-free
} // namespace

__global__ void __launch_bounds__(TPB, 8) prnn_kernel(
    const float* __restrict__ x,    // [B,S,3]
    const float* __restrict__ W1,   // [384,3]
    const float* __restrict__ W2,   // [3,384]
    float* __restrict__ out)        // [B,S,3]
{
    const float TWO_MU   = (float)(2.0 * (3130.0 / (2.0 * 1.3)));
    const float THREE_MU = (float)(3.0 * (3130.0 / (2.0 * 1.3)));
    const float INV_3MU  = (float)(1.0 / (3.0 * (3130.0 / (2.0 * 1.3))));
    const float LAM      = (float)(3130.0 * 0.3 / (1.3 * 0.4));
    const float Ah = 64.8f, Bh = 33.6f;
    const float INV_C = (float)(1.0 / 0.003407);
    const float BC    = (float)(33.6 / 0.003407);
    const float KTH   = 20.0f * 0.003407f;   // beyond this, B*exp(-k/C) < 7e-8

    __shared__ float sx[Ss * 3];             // 6 KB
    __shared__ float part[T * ROW];          // 12.4 KB

    const int b   = blockIdx.x;
    const int tid = threadIdx.x;
    const int t3  = 3 * tid;

    const float* xb = x + (long)b * (Ss * 3);
    for (int i = tid; i < Ss * 3; i += TPB) sx[i] = xb[i];

    float w1[9], w2[9];
#pragma unroll
    for (int i = 0; i < 9; ++i) w1[i] = W1[tid * 9 + i];
#pragma unroll
    for (int o = 0; o < 3; ++o)
#pragma unroll
        for (int j = 0; j < 3; ++j) w2[o * 3 + j] = W2[o * 384 + t3 + j];

    float ep0 = 0.f, ep1 = 0.f, ep2 = 0.f, ep3 = 0.f, kap = 0.f;
    float* outb = out + (long)b * (Ss * 3);

    __syncthreads();

    for (int s0 = 0; s0 < Ss; s0 += T) {
#pragma unroll 1
        for (int si = 0; si < T; ++si) {
            const int s = s0 + si;
            const float x0 = sx[3 * s + 0];
            const float x1 = sx[3 * s + 1];
            const float x2 = sx[3 * s + 2];

            // fc1
            const float e0 = w1[0] * x0 + w1[1] * x1 + w1[2] * x2;
            const float e1 = w1[3] * x0 + w1[4] * x1 + w1[5] * x2;
            const float g2 = w1[6] * x0 + w1[7] * x1 + w1[8] * x2;

            // elastic trial (Voigt-4 tensorial: xx, yy, zz, xy)
            const float ee0 = e0 - ep0;
            const float ee1 = e1 - ep1;
            const float ee2 = -ep2;
            const float ee3 = 0.5f * g2 - ep3;
            const float lt  = LAM * (ee0 + ee1 + ee2);
            float sg0 = TWO_MU * ee0 + lt;
            float sg1 = TWO_MU * ee1 + lt;
            float sg2 = TWO_MU * ee2 + lt;
            float sg3 = TWO_MU * ee3;
            const float p  = (sg0 + sg1 + sg2) * (1.0f / 3.0f);
            const float s0d = sg0 - p, s1d = sg1 - p, s2d = sg2 - p, s3d = sg3;

            float qsq = 1.5f * (s0d * s0d + s1d * s1d + s2d * s2d + 2.f * s3d * s3d);
            qsq = fmaxf(qsq, 1e-24f);
            const float rq = rsqrtf(qsq);     // 1/q
            const float q  = qsq * rq;        // q

            // yield check; skip exp when it's saturated (late) or exactly 1 (early)
            float bex;
            if (__all_sync(0xffffffffu, kap > KTH)) {
                bex = 0.f;
            } else if (__all_sync(0xffffffffu, kap == 0.f)) {
                bex = Bh;
            } else {
                bex = Bh * __expf(-kap * INV_C);
            }
            const float f = q - Ah + bex;
            const bool plastic = f > 0.f;

            float dg = 0.f;
            if (__any_sync(0xffffffffu, plastic)) {
                const bool easy = kap > KTH;  // exp term negligible -> linear root
                float dgv = easy ? fmaxf((q - Ah) * INV_3MU, 0.f) : 0.f;
                if (!__all_sync(0xffffffffu, easy)) {
#pragma unroll 1
                    for (int it = 0; it < 12; ++it) {
                        const float ek  = __expf(-(kap + dgv) * INV_C);
                        const float r   = q - THREE_MU * dgv - Ah + Bh * ek;
                        const float dr  = THREE_MU + BC * ek;     // = -f'
                        const float dgn = fmaxf(dgv + __fdividef(r, dr), 0.f);
                        const bool done = fabsf(dgn - dgv) <= (1e-10f + 4e-7f * dgn);
                        dgv = dgn;
                        if (__all_sync(0xffffffffu, done)) break;
                    }
                }
                dg = plastic ? dgv : 0.f;
            }

            // radial return + state update
            const float c  = dg * rq;
            const float a3 = THREE_MU * c;
            sg0 -= a3 * s0d;
            sg1 -= a3 * s1d;
            sg3 -= a3 * s3d;
            const float bc = 1.5f * c;
            ep0 += bc * s0d;
            ep1 += bc * s1d;
            ep2 += bc * s2d;
            ep3 += bc * s3d;
            kap += dg;

            // output projection partials -> smem (stride-3 across lanes: conflict-free)
            float* pr = part + si * ROW + t3;
            pr[0] = w2[0] * sg0 + w2[1] * sg1 + w2[2] * sg3;
            pr[1] = w2[3] * sg0 + w2[4] * sg1 + w2[5] * sg3;
            pr[2] = w2[6] * sg0 + w2[7] * sg1 + w2[8] * sg3;
        }
        __syncthreads();

        // 24 threads: each sums 128 partials for one (step, output) pair.
        // addr = si*388 + o + 3m: (4*si + o) mod 32 distinct for all 24 -> no conflicts.
        if (tid < 3 * T) {
            const int si = tid / 3;
            const int o  = tid - 3 * si;
            const float* pr = part + si * ROW + o;
            float a0 = 0.f, a1 = 0.f, a2 = 0.f, a3 = 0.f;
#pragma unroll 8
            for (int m = 0; m < TPB; m += 4) {
                a0 += pr[3 * m];
                a1 += pr[3 * (m + 1)];
                a2 += pr[3 * (m + 2)];
                a3 += pr[3 * (m + 3)];
            }
            outb[s0 * 3 + tid] = (a0 + a1) + (a2 + a3);
        }
        __syncthreads();
    }
}

extern "C" void kernel_launch(void* const* d_in, const int* in_sizes, int n_in,
                              void* d_out, int out_size) {
    const float* x  = (const float*)d_in[0];
    const float* W1 = (const float*)d_in[1];
    const float* W2 = (const float*)d_in[2];
    prnn_kernel<<<Bb, TPB>>>(x, W1, W2, (float*)d_out);
}

// round 3
// speedup vs baseline: 1.7060x; 1.3672x over previous
#include <cuda_runtime.h>

// PRNN_1769526526374: J2 plane-strain plasticity RNN.
// R3: f32x2 packed math, 2 batch elements per thread (same material point,
// shared weights). Cached hardening term (bex = B*exp(-kappa/C)) so elastic
// steps need no MUFU exp; Newton seeded from cached bex + 2 fixed iterations.

namespace {
constexpr int Bb  = 4096;
constexpr int Ss  = 512;
constexpr int TPB = 128;
constexpr int T   = 8;              // steps per reduction chunk
constexpr int ROW = 3 * TPB + 2;    // in float2 units

typedef unsigned long long F2;

__device__ __forceinline__ F2 pk2(float lo, float hi) {
    F2 r; asm("mov.b64 %0, {%1, %2};" : "=l"(r) : "f"(lo), "f"(hi)); return r;
}
__device__ __forceinline__ void upk2(F2 v, float& lo, float& hi) {
    asm("mov.b64 {%0, %1}, %2;" : "=f"(lo), "=f"(hi) : "l"(v));
}
__device__ __forceinline__ F2 mul2(F2 a, F2 b) {
    F2 r; asm("mul.rn.f32x2 %0, %1, %2;" : "=l"(r) : "l"(a), "l"(b)); return r;
}
__device__ __forceinline__ F2 add2(F2 a, F2 b) {
    F2 r; asm("add.rn.f32x2 %0, %1, %2;" : "=l"(r) : "l"(a), "l"(b)); return r;
}
__device__ __forceinline__ F2 fma2(F2 a, F2 b, F2 c) {
    F2 r; asm("fma.rn.f32x2 %0, %1, %2, %3;" : "=l"(r) : "l"(a), "l"(b), "l"(c)); return r;
}

__constant__ float c_dummy;  // (nothing)
} // namespace

__global__ void __launch_bounds__(TPB, 4) prnn_kernel(
    const float* __restrict__ x,    // [B,S,3]
    const float* __restrict__ W1,   // [384,3]
    const float* __restrict__ W2,   // [3,384]
    float* __restrict__ out)        // [B,S,3]
{
    const float MUv      = (float)(3130.0 / (2.0 * 1.3));
    const float TWO_MU   = (float)(2.0 * (3130.0 / (2.0 * 1.3)));
    const float THREE_MU = (float)(3.0 * (3130.0 / (2.0 * 1.3)));
    const float LAM      = (float)(3130.0 * 0.3 / (1.3 * 0.4));
    const float Ah = 64.8f, Bh = 33.6f;
    const float INV_C = (float)(1.0 / 0.003407);
    const float BC    = (float)(33.6 / 0.003407);
    (void)MUv;

    const F2 HALF2    = pk2(0.5f, 0.5f);
    const F2 TWO_MU2  = pk2(TWO_MU, TWO_MU);
    const F2 LAM2     = pk2(LAM, LAM);
    const F2 NTHIRD2  = pk2(-1.0f / 3.0f, -1.0f / 3.0f);
    const F2 ONEP5_2  = pk2(1.5f, 1.5f);
    const F2 THREE2   = pk2(3.0f, 3.0f);

    __shared__ F2 sx2[Ss * 3];        // 12 KB, packed (b0, b1)
    __shared__ F2 part[T * ROW];      // 24.1 KB, packed partials

    const int tid = threadIdx.x;
    const int t3  = 3 * tid;
    const int b0  = 2 * blockIdx.x;

    const float* xb0 = x + (long)b0 * (Ss * 3);
    const float* xb1 = xb0 + Ss * 3;
    for (int i = tid; i < Ss * 3; i += TPB) sx2[i] = pk2(xb0[i], xb1[i]);

    // Weights for material point m = tid, replicated into both halves.
    F2 w1p[9], w2p[9];
#pragma unroll
    for (int i = 0; i < 9; ++i) { float w = W1[tid * 9 + i]; w1p[i] = pk2(w, w); }
#pragma unroll
    for (int o = 0; o < 3; ++o)
#pragma unroll
        for (int j = 0; j < 3; ++j) {
            float w = W2[o * 384 + t3 + j];
            w2p[o * 3 + j] = pk2(w, w);
        }

    // State: negated tensorial plastic strain (packed), kappa + cached
    // (B*exp(-kappa/C) - A) per half.
    F2 nep0 = 0, nep1 = 0, nep2 = 0, nep3 = 0;
    float kapA = 0.f, kapB = 0.f;
    float bexmA = Bh - Ah, bexmB = Bh - Ah;

    float* outb0 = out + (long)b0 * (Ss * 3);
    float* outb1 = outb0 + Ss * 3;

    __syncthreads();

    for (int s0 = 0; s0 < Ss; s0 += T) {
#pragma unroll 1
        for (int si = 0; si < T; ++si) {
            const int s = s0 + si;
            const F2 x0 = sx2[3 * s + 0];
            const F2 x1 = sx2[3 * s + 1];
            const F2 x2 = sx2[3 * s + 2];

            // fc1 (both halves at once)
            const F2 e0 = fma2(w1p[0], x0, fma2(w1p[1], x1, mul2(w1p[2], x2)));
            const F2 e1 = fma2(w1p[3], x0, fma2(w1p[4], x1, mul2(w1p[5], x2)));
            const F2 g2 = fma2(w1p[6], x0, fma2(w1p[7], x1, mul2(w1p[8], x2)));

            // elastic trial (Voigt-4 tensorial: xx, yy, zz, xy)
            const F2 ee0 = add2(e0, nep0);
            const F2 ee1 = add2(e1, nep1);
            const F2 ee3 = fma2(g2, HALF2, nep3);   // 0.5*gxy - ep3
            const F2 tr  = add2(add2(ee0, ee1), nep2);
            const F2 lt  = mul2(LAM2, tr);
            F2 sg0 = fma2(TWO_MU2, ee0, lt);
            F2 sg1 = fma2(TWO_MU2, ee1, lt);
            F2 sg2 = fma2(TWO_MU2, nep2, lt);
            F2 sg3 = mul2(TWO_MU2, ee3);

            const F2 np  = mul2(NTHIRD2, add2(add2(sg0, sg1), sg2));
            const F2 s0d = add2(sg0, np);
            const F2 s1d = add2(sg1, np);
            const F2 s2d = add2(sg2, np);
            const F2 s3d = sg3;

            F2 acc = mul2(s0d, s0d);
            acc = fma2(s1d, s1d, acc);
            acc = fma2(s2d, s2d, acc);
            const F2 bsq  = mul2(s3d, s3d);
            const F2 qsq2 = fma2(ONEP5_2, acc, mul2(THREE2, bsq));

            float qsA, qsB;
            upk2(qsq2, qsA, qsB);
            const float qmA = fmaxf(qsA, 1e-24f);
            const float qmB = fmaxf(qsB, 1e-24f);
            const float rqA = rsqrtf(qmA);
            const float rqB = rsqrtf(qmB);
            const float qA  = qmA * rqA;
            const float qB  = qmB * rqB;

            const float fA = qA + bexmA;   // q - (A - B*exp(-kap/C))
            const float fB = qB + bexmB;

            if (__any_sync(0xffffffffu, (fA > 0.f) | (fB > 0.f))) {
                // Seed = exact first Newton iteration from dg=0 using cached
                // bex (no exp); then 2 fixed iterations (quadratic: converged
                // past f32 precision, same root as reference's 12 iters).
                float dgA = __fdividef(fmaxf(fA, 0.f),
                                       THREE_MU + (bexmA + Ah) * INV_C);
                float dgB = __fdividef(fmaxf(fB, 0.f),
                                       THREE_MU + (bexmB + Ah) * INV_C);
#pragma unroll
                for (int it = 0; it < 2; ++it) {
                    const float ekA = __expf(-(kapA + dgA) * INV_C);
                    const float ekB = __expf(-(kapB + dgB) * INV_C);
                    const float rA  = qA - THREE_MU * dgA - Ah + Bh * ekA;
                    const float rB  = qB - THREE_MU * dgB - Ah + Bh * ekB;
                    dgA = fmaxf(dgA + __fdividef(rA, THREE_MU + BC * ekA), 0.f);
                    dgB = fmaxf(dgB + __fdividef(rB, THREE_MU + BC * ekB), 0.f);
                }
                kapA += dgA;
                kapB += dgB;
                bexmA = Bh * __expf(-kapA * INV_C) - Ah;
                bexmB = Bh * __expf(-kapB * INV_C) - Ah;

                // packed radial return + state update (no-op where dg == 0)
                const float cA = dgA * rqA, cB = dgB * rqB;
                const F2 NA2 = pk2(-THREE_MU * cA, -THREE_MU * cB);
                const F2 NB2 = pk2(-1.5f * cA, -1.5f * cB);
                nep0 = fma2(NB2, s0d, nep0);
                nep1 = fma2(NB2, s1d, nep1);
                nep2 = fma2(NB2, s2d, nep2);
                nep3 = fma2(NB2, s3d, nep3);
                sg0  = fma2(NA2, s0d, sg0);
                sg1  = fma2(NA2, s1d, sg1);
                sg3  = fma2(NA2, s3d, sg3);
            }

            // output projection partials (packed) -> smem
            const F2 p0 = fma2(w2p[0], sg0, fma2(w2p[1], sg1, mul2(w2p[2], sg3)));
            const F2 p1 = fma2(w2p[3], sg0, fma2(w2p[4], sg1, mul2(w2p[5], sg3)));
            const F2 p2 = fma2(w2p[6], sg0, fma2(w2p[7], sg1, mul2(w2p[8], sg3)));
            F2* pr = part + si * ROW + t3;
            pr[0] = p0;
            pr[1] = p1;
            pr[2] = p2;
        }
        __syncthreads();

        // 24 threads: each sums 128 packed partials for one (step, output).
        if (tid < 3 * T) {
            const int si = tid / 3;
            const int o  = tid - 3 * si;
            const F2* pr = part + si * ROW + o;
            F2 a0 = 0, a1 = 0, a2 = 0, a3 = 0;
#pragma unroll 8
            for (int m = 0; m < TPB; m += 4) {
                a0 = add2(a0, pr[3 * m]);
                a1 = add2(a1, pr[3 * (m + 1)]);
                a2 = add2(a2, pr[3 * (m + 2)]);
                a3 = add2(a3, pr[3 * (m + 3)]);
            }
            const F2 t = add2(add2(a0, a1), add2(a2, a3));
            float lo, hi;
            upk2(t, lo, hi);
            outb0[s0 * 3 + tid] = lo;
            outb1[s0 * 3 + tid] = hi;
        }
        __syncthreads();
    }
}

extern "C" void kernel_launch(void* const* d_in, const int* in_sizes, int n_in,
                              void* d_out, int out_size) {
    const float* x  = (const float*)d_in[0];
    const float* W1 = (const float*)d_in[1];
    const float* W2 = (const float*)d_in[2];
    prnn_kernel<<<Bb / 2, TPB>>>(x, W1, W2, (float*)d_out);
}